// round 13
// baseline (speedup 1.0000x reference)
#include <cuda_runtime.h>
#include <cstdint>

#define NT1      128
#define MTILE    64
#define NH       64
#define NB       64
#define DIMC     1024

// k32 pipeline stage: A_hi 4K + A_lo 4K + B frags 8K
#define STAGE    16384
#define AHI      0
#define ALO      4096
#define BOFF     8192
// epilogue overlay smem
#define OFF_ZS   0              // float[64*66] = 16896 B
#define OFF_OWT  16896          // float[64*64] = 16384 B
#define OFF_P1   33280
#define OFF_P2   34304
#define SMEM_TOTAL 35328        // > 2*STAGE = 32768

__device__ float4 g_q[NH * NB];
__device__ float  g_owt[NH * NB];          // out_weight transposed [k][h]
__device__ float4 g_p1[NH];                // {c0', sq, d, A}
__device__ float4 g_p2[NH];                // {B, 2B, 2^{2B}, 0}
__device__ int    g_bad = 0;
// B fragments in MMA order: [ks 0..63][nt8 0..7][lane 0..31] x uint4{bh0,bh1,bl0,bl1}
__device__ __align__(16) unsigned char g_bf[64 * 8 * 512];

static __device__ __forceinline__ uint32_t smem_u32(const void* p) {
    uint32_t a;
    asm("{ .reg .u64 t; cvta.to.shared.u64 t, %1; cvt.u32.u64 %0, t; }" : "=r"(a) : "l"(p));
    return a;
}

#define FMA2(acc, a, b) asm("fma.rn.f32x2 %0, %1, %2, %0;" : "+l"(acc) : "l"(a), "l"(b))
#define MUL2(d, a, b)   asm("mul.rn.f32x2 %0, %1, %2;" : "=l"(d) : "l"(a), "l"(b))
#define PACK2(d, lo, hi) asm("mov.b64 %0, {%1, %2};" : "=l"(d) : "f"(lo), "f"(hi))

#define CP_ASYNC16(dst, src) \
    asm volatile("cp.async.ca.shared.global [%0], [%1], 16;" :: "r"(dst), "l"(src) : "memory")
#define CP_COMMIT() asm volatile("cp.async.commit_group;" ::: "memory")
#define CP_WAIT0()  asm volatile("cp.async.wait_group 0;" ::: "memory")

#define LDG128CS(v, p) \
    asm volatile("ld.global.cs.v4.f32 {%0,%1,%2,%3}, [%4];" \
                 : "=f"((v).x), "=f"((v).y), "=f"((v).z), "=f"((v).w) : "l"(p))

#define LDSM4(r0, r1, r2, r3, a) \
    asm volatile("ldmatrix.sync.aligned.m8n8.x4.shared.b16 {%0,%1,%2,%3}, [%4];" \
                 : "=r"(r0), "=r"(r1), "=r"(r2), "=r"(r3) : "r"(a))
#define LDS128U(u, a) \
    asm volatile("ld.shared.v4.b32 {%0,%1,%2,%3}, [%4];" \
                 : "=r"((u).x), "=r"((u).y), "=r"((u).z), "=r"((u).w) : "r"(a))

#define MMA(c, a0, a1, a2, a3, b0, b1) \
    asm volatile("mma.sync.aligned.m16n8k16.row.col.f32.bf16.bf16.f32 " \
                 "{%0,%1,%2,%3}, {%4,%5,%6,%7}, {%8,%9}, {%0,%1,%2,%3};" \
                 : "+f"((c)[0]), "+f"((c)[1]), "+f"((c)[2]), "+f"((c)[3]) \
                 : "r"(a0), "r"(a1), "r"(a2), "r"(a3), "r"(b0), "r"(b1))

// fp32 pair -> bf16x2 hi (truncation) + bf16x2 lo (residual)
static __device__ __forceinline__ void cvt_pair(float2 f, uint32_t& hi, uint32_t& lo) {
    uint32_t u0 = __float_as_uint(f.x), u1 = __float_as_uint(f.y);
    hi = __byte_perm(u0, u1, 0x7632);
    float l0 = f.x - __uint_as_float(u0 & 0xffff0000u);
    float l1 = f.y - __uint_as_float(u1 & 0xffff0000u);
    asm("cvt.rn.bf16x2.f32 %0, %1, %2;" : "=r"(lo) : "f"(l1), "f"(l0));
}

// split 8 consecutive k (two float4) -> one 16B hi STS.128 + one 16B lo STS.128
static __device__ __forceinline__ void split_store128(float4 v0, float4 v1,
                                                      uint32_t ahi, uint32_t alo) {
    uint32_t h0, l0, h1, l1, h2, l2, h3, l3;
    cvt_pair(make_float2(v0.x, v0.y), h0, l0);
    cvt_pair(make_float2(v0.z, v0.w), h1, l1);
    cvt_pair(make_float2(v1.x, v1.y), h2, l2);
    cvt_pair(make_float2(v1.z, v1.w), h3, l3);
    asm volatile("st.shared.v4.b32 [%0], {%1,%2,%3,%4};"
                 :: "r"(ahi), "r"(h0), "r"(h1), "r"(h2), "r"(h3) : "memory");
    asm volatile("st.shared.v4.b32 [%0], {%1,%2,%3,%4};"
                 :: "r"(alo), "r"(l0), "r"(l1), "r"(l2), "r"(l3) : "memory");
}

// ---- prep: blocks 0-63 build B fragment table; blocks 64-79 coeff tables ----
__global__ void rbf_prep(const float* __restrict__ in_b,
                         const float* __restrict__ centers,
                         const float* __restrict__ log_widths,
                         const float* __restrict__ out_weight,
                         const float* __restrict__ in_w)
{
    const int bid = blockIdx.x;
    const int tid = threadIdx.x;

    if (bid < 64) {
        int t = bid * 256 + tid;          // 0..16383
        int ks   = t >> 8;
        int nt8  = (t >> 5) & 7;
        int lane = t & 31;
        int n  = nt8 * 8 + (lane >> 2);
        int kk = ks * 16 + 2 * (lane & 3);
        const float* wr = in_w + n * DIMC + kk;
        uint32_t bh0, bl0, bh1, bl1;
        cvt_pair(make_float2(wr[0], wr[1]), bh0, bl0);
        cvt_pair(make_float2(wr[8], wr[9]), bh1, bl1);
        *(uint4*)(g_bf + (size_t)(ks * 8 + nt8) * 512 + lane * 16) =
            make_uint4(bh0, bh1, bl0, bl1);
        return;
    }

    const int i = (bid - 64) * 256 + tid;   // 0..4095
    const int h = i >> 6;
    const int k = i & 63;

    float lw = log_widths[i];
    float sp = (lw > 15.f) ? lw : log1pf(expf(lw));
    float w = sp + 0.001f;
    float s = -1.4426950408889634f / (w * w);
    float c = centers[i] - in_b[h];
    float4 q;
    q.x = s; q.y = -2.f * s * c; q.z = s * c * c; q.w = out_weight[i];
    g_q[i] = q;
    g_owt[i] = out_weight[((i & 63) << 6) + (i >> 6)];

    float c0  = centers[h * NB];
    float d   = (centers[h * NB + NB - 1] - c0) / (float)(NB - 1);
    float lw0 = log_widths[h * NB];
    bool ok = (fabsf(centers[i] - fmaf((float)k, d, c0)) <= 1e-5f) &&
              (fabsf(lw - lw0) <= 1e-6f);
    if (!ok) atomicAdd(&g_bad, 1);

    if (k == 0) {
        float sp0 = (lw0 > 15.f) ? lw0 : log1pf(expf(lw0));
        float w0  = sp0 + 0.001f;
        float sq  = -1.4426950408889634f / (w0 * w0);
        float A   = -2.f * sq * d;
        float B   = sq * d * d;
        float4 p1, p2;
        p1.x = c0 - in_b[h]; p1.y = sq; p1.z = d; p1.w = A;
        p2.x = B; p2.y = 2.f * B; p2.z = exp2f(2.f * B); p2.w = 0.f;
        g_p1[h] = p1; g_p2[h] = p2;
    }
}

// ---- fused GEMM + RBF: MTILE=64, k32 double-buffered, 6 CTAs/SM ----
__global__ void __launch_bounds__(NT1, 6)
rbf_fused_kernel(const float* __restrict__ x,
                 const float* __restrict__ out_bias,
                 float* __restrict__ out)
{
    extern __shared__ char smem[];
    const uint32_t sb = smem_u32(smem);
    const int tid = threadIdx.x;
    const int wid = tid >> 5;
    const int l   = tid & 31;
    const int wq  = wid & 1;              // token half (32 tok)
    const int wh  = wid >> 1;             // h half (32 h)
    const int tok0 = blockIdx.x * MTILE;

    float acc[2][4][4];
#pragma unroll
    for (int m = 0; m < 2; ++m)
#pragma unroll
        for (int nt = 0; nt < 4; ++nt)
#pragma unroll
            for (int j = 0; j < 4; ++j) acc[m][nt][j] = 0.f;

    // --- producer constants (A: thread handles rows pr, pr+32; 8 consecutive k) ---
    const int pr = tid >> 2;               // 0..31 base row
    const int pg = tid & 3;                // k8 group within chunk
    const uint32_t pcol = (uint32_t)((pg ^ ((pr >> 1) & 3)) << 4);
    const float* xbase = x + (size_t)(tok0 + pr) * DIMC + pg * 8;
    // B producer: 64B per thread
    const char* bsrc = (const char*)g_bf + (size_t)tid * 64;
    const uint32_t bdst = BOFF + (uint32_t)tid * 64;

    // --- consumer constants ---
    const uint32_t rowA = (uint32_t)(wq * 32 + (l & 15));
    const uint32_t chA  = (uint32_t)(l >> 4);
    const uint32_t key2 = ((uint32_t)(l & 15) >> 1) & 3u;
    const uint32_t aoff = rowA * 64u;
    const uint32_t boff = BOFF + (uint32_t)(wh * 4) * 512u + (uint32_t)l * 16u;

    float4 pa[2][2];                       // [row group it][float4 half]

    // ---- prologue: chunk 0 into stage 0 ----
#pragma unroll
    for (int it = 0; it < 2; ++it) {
        const float* p = xbase + (size_t)(32 * it) * DIMC;
        LDG128CS(pa[it][0], p);
        LDG128CS(pa[it][1], p + 4);
    }
#pragma unroll
    for (int it = 0; it < 2; ++it) {
        uint32_t ad = (uint32_t)(pr + 32 * it) * 64u + pcol;
        split_store128(pa[it][0], pa[it][1], sb + AHI + ad, sb + ALO + ad);
    }
#pragma unroll
    for (int c = 0; c < 4; ++c)
        CP_ASYNC16(sb + bdst + c * 16, bsrc + c * 16);
    CP_COMMIT();

#pragma unroll 1
    for (int i = 0; i < 32; ++i) {
        const uint32_t sbase = sb + (uint32_t)(i & 1) * STAGE;
        const uint32_t dbase = sb + (uint32_t)((i + 1) & 1) * STAGE;

        CP_WAIT0();
        __syncthreads();

        if (i < 31) {
            const float* xc = xbase + (size_t)(i + 1) * 32;
#pragma unroll
            for (int it = 0; it < 2; ++it) {
                const float* p = xc + (size_t)(32 * it) * DIMC;
                LDG128CS(pa[it][0], p);
                LDG128CS(pa[it][1], p + 4);
            }
#pragma unroll
            for (int c = 0; c < 4; ++c)
                CP_ASYNC16(dbase + bdst + c * 16, bsrc + (size_t)(i + 1) * 8192 + c * 16);
            CP_COMMIT();
        }

#pragma unroll
        for (int s2 = 0; s2 < 2; ++s2) {
            const uint32_t colA = (((uint32_t)(s2 * 2) + chA) ^ key2) << 4;
            uint32_t ah[2][4], al[2][4];
#pragma unroll
            for (int m = 0; m < 2; ++m) {
                uint32_t ra = sbase + aoff + (uint32_t)m * 1024u + colA;
                LDSM4(ah[m][0], ah[m][1], ah[m][2], ah[m][3], ra + AHI);
                LDSM4(al[m][0], al[m][1], al[m][2], al[m][3], ra + ALO);
            }
#pragma unroll
            for (int nt = 0; nt < 4; ++nt) {
                uint4 b;
                LDS128U(b, sbase + boff + (uint32_t)(s2 * 4096) + (uint32_t)nt * 512u);
#pragma unroll
                for (int m = 0; m < 2; ++m) {
                    MMA(acc[m][nt], ah[m][0], ah[m][1], ah[m][2], ah[m][3], b.x, b.y);
                    MMA(acc[m][nt], ah[m][0], ah[m][1], ah[m][2], ah[m][3], b.z, b.w);
                    MMA(acc[m][nt], al[m][0], al[m][1], al[m][2], al[m][3], b.x, b.y);
                }
            }
            if (s2 == 1 && i < 31) {
#pragma unroll
                for (int it = 0; it < 2; ++it) {
                    uint32_t ad = (uint32_t)(pr + 32 * it) * 64u + pcol;
                    split_store128(pa[it][0], pa[it][1], dbase + AHI + ad, dbase + ALO + ad);
                }
            }
        }
    }
    __syncthreads();

    // ---- overlay: z -> smem [64][66], stage tables ----
    {
        float* zs = (float*)(smem + OFF_ZS);
        const int g = l >> 2, t = l & 3;
#pragma unroll
        for (int m = 0; m < 2; ++m)
#pragma unroll
            for (int nt = 0; nt < 4; ++nt) {
                int tok = wq * 32 + m * 16 + g;
                int hcol = wh * 32 + nt * 8 + 2 * t;
                *(float2*)(zs + tok * 66 + hcol)       = make_float2(acc[m][nt][0], acc[m][nt][1]);
                *(float2*)(zs + (tok + 8) * 66 + hcol) = make_float2(acc[m][nt][2], acc[m][nt][3]);
            }
        float4* owt = (float4*)(smem + OFF_OWT);
        const float4* gow = (const float4*)g_owt;
#pragma unroll
        for (int j = 0; j < 8; ++j) owt[j * NT1 + tid] = gow[j * NT1 + tid];
        if (tid < NH) {
            ((float4*)(smem + OFF_P1))[tid] = g_p1[tid];
            ((float4*)(smem + OFF_P2))[tid] = g_p2[tid];
        }
    }
    __syncthreads();

    // ---- epilogue: thread = 4 tokens x 8 h ----
    const int hq = tid & 7;
    const int p  = tid >> 3;               // tokens p + 16*j
    const float* zs = (const float*)(smem + OFF_ZS);
    const float4* p1s = (const float4*)(smem + OFF_P1);
    const float4* p2s = (const float4*)(smem + OFF_P2);
    float sum[4];

    if (g_bad == 0) {
        unsigned long long acc2[4] = {0ull, 0ull, 0ull, 0ull};
#pragma unroll
        for (int hp = 0; hp < 4; ++hp) {
            const int h0 = hq * 8 + 2 * hp;
            float4 Pa = p1s[h0], Pb = p1s[h0 + 1];
            float4 Qa = p2s[h0], Qb = p2s[h0 + 1];
            unsigned long long tt;
            PACK2(tt, Qa.z, Qb.z);
            float u0[4], u1[4], rb0[4], rb1[4];
#pragma unroll
            for (int j = 0; j < 4; ++j) {
                float2 zz = *(const float2*)(zs + (p + 16 * j) * 66 + h0);
                u0[j] = zz.x - Pa.x;  u1[j] = zz.y - Pb.x;
                rb0[j] = fmaf(Pa.w, u0[j], Qa.x);
                rb1[j] = fmaf(Pb.w, u1[j], Qb.x);
            }
            const uint32_t owbase = sb + OFF_OWT + (uint32_t)h0 * 4u;
#pragma unroll
            for (int m = 0; m < 4; ++m) {
                const float km = (float)(16 * m);
                unsigned long long e[4], r[4];
#pragma unroll
                for (int j = 0; j < 4; ++j) {
                    float v0 = fmaf(-km, Pa.z, u0[j]);
                    float v1 = fmaf(-km, Pb.z, u1[j]);
                    float e0, e1, rr0, rr1;
                    float a0 = Pa.y * v0 * v0, a1 = Pb.y * v1 * v1;
                    asm("ex2.approx.f32 %0, %1;" : "=f"(e0) : "f"(a0));
                    asm("ex2.approx.f32 %0, %1;" : "=f"(e1) : "f"(a1));
                    float b0 = fmaf(km, Qa.y, rb0[j]), b1 = fmaf(km, Qb.y, rb1[j]);
                    asm("ex2.approx.f32 %0, %1;" : "=f"(rr0) : "f"(b0));
                    asm("ex2.approx.f32 %0, %1;" : "=f"(rr1) : "f"(b1));
                    PACK2(e[j], e0, e1);
                    PACK2(r[j], rr0, rr1);
                }
                uint32_t a = owbase + (uint32_t)m * (16u * 256u);
#pragma unroll
                for (int kk = 0; kk < 16; ++kk) {
                    unsigned long long w2;
                    asm volatile("ld.shared.b64 %0, [%1];" : "=l"(w2) : "r"(a));
                    a += 256u;
#pragma unroll
                    for (int j = 0; j < 4; ++j) {
                        FMA2(acc2[j], e[j], w2);
                        MUL2(e[j], e[j], r[j]);
                        MUL2(r[j], r[j], tt);
                    }
                }
            }
        }
#pragma unroll
        for (int j = 0; j < 4; ++j) {
            float lo, hi;
            asm("mov.b64 {%0,%1}, %2;" : "=f"(lo), "=f"(hi) : "l"(acc2[j]));
            sum[j] = lo + hi;
        }
    } else {
#pragma unroll
        for (int j = 0; j < 4; ++j) sum[j] = 0.f;
#pragma unroll 1
        for (int i = 0; i < 8; ++i) {
            const int h = hq * 8 + i;
            const float4* qh = g_q + h * NB;
            float zh[4];
#pragma unroll
            for (int j = 0; j < 4; ++j) zh[j] = zs[(p + 16 * j) * 66 + h];
#pragma unroll 8
            for (int k = 0; k < NB; ++k) {
                float4 q = qh[k];
#pragma unroll
                for (int j = 0; j < 4; ++j) {
                    float pp = fmaf(fmaf(q.x, zh[j], q.y), zh[j], q.z);
                    float e;
                    asm("ex2.approx.f32 %0, %1;" : "=f"(e) : "f"(pp));
                    sum[j] = fmaf(e, q.w, sum[j]);
                }
            }
        }
    }

    const float ob = __ldg(out_bias);
#pragma unroll
    for (int j = 0; j < 4; ++j) {
        float v = sum[j];
        v += __shfl_xor_sync(0xffffffffu, v, 1);
        v += __shfl_xor_sync(0xffffffffu, v, 2);
        v += __shfl_xor_sync(0xffffffffu, v, 4);
        if (hq == 0) out[tok0 + p + 16 * j] = v + ob;
    }
}

extern "C" void kernel_launch(void* const* d_in, const int* in_sizes, int n_in,
                              void* d_out, int out_size)
{
    const float* x          = (const float*)d_in[0];
    const float* in_w       = (const float*)d_in[1];
    const float* in_b       = (const float*)d_in[2];
    const float* centers    = (const float*)d_in[3];
    const float* log_widths = (const float*)d_in[4];
    const float* out_weight = (const float*)d_in[5];
    const float* out_bias   = (const float*)d_in[6];
    float* out = (float*)d_out;

    int ntok = in_sizes[0] / DIMC;          // 65536

    rbf_prep<<<80, 256>>>(in_b, centers, log_widths, out_weight, in_w);

    cudaFuncSetAttribute(rbf_fused_kernel,
                         cudaFuncAttributeMaxDynamicSharedMemorySize, SMEM_TOTAL);
    rbf_fused_kernel<<<ntok / MTILE, NT1, SMEM_TOTAL>>>(x, out_bias, out);
}

// round 14
// speedup vs baseline: 1.4612x; 1.4612x over previous
#include <cuda_runtime.h>
#include <cstdint>

#define NT1      256
#define MTILE    128
#define NCHUNKS  16
#define NH       64
#define NB       64
#define DIMC     1024

// stage layout (two stages) — R8 proven GEMM config
#define STAGE_BYTES 49152
#define OFF_AHI  0
#define OFF_ALO  16384
#define OFF_BHI  32768          // B hi (8 KB) + B lo (8 KB) contiguous
// post-GEMM overlay
#define OFF_ZS   0              // float[128*66] = 33792 B
#define SMEM_TOTAL (2 * STAGE_BYTES)

#define TBLN     4096           // grid points over [-8, 8), step 1/256
#define TSCALE   256.0f
#define TOFF     2048.0f

__device__ float4 g_q[NH * NB];            // {s, -2sc', sc'^2, ow} (bias folded)
__device__ float2 g_tbl[NH * TBLN];        // per-h score table {f_i, f_{i+1}}
__device__ __align__(16) unsigned char g_wt[NCHUNKS * 16384];  // pre-split W tiles

static __device__ __forceinline__ uint32_t smem_u32(const void* p) {
    uint32_t a;
    asm("{ .reg .u64 t; cvta.to.shared.u64 t, %1; cvt.u32.u64 %0, t; }" : "=r"(a) : "l"(p));
    return a;
}

#define CP_ASYNC16(dst, src) \
    asm volatile("cp.async.ca.shared.global [%0], [%1], 16;" :: "r"(dst), "l"(src) : "memory")
#define CP_COMMIT() asm volatile("cp.async.commit_group;" ::: "memory")
#define CP_WAIT0()  asm volatile("cp.async.wait_group 0;" ::: "memory")

static __device__ __forceinline__ void split_pack(float4 v, uint32_t& hi01, uint32_t& hi23,
                                                  uint32_t& lo01, uint32_t& lo23) {
    uint32_t u0 = __float_as_uint(v.x), u1 = __float_as_uint(v.y);
    uint32_t u2 = __float_as_uint(v.z), u3 = __float_as_uint(v.w);
    hi01 = __byte_perm(u0, u1, 0x7632);
    hi23 = __byte_perm(u2, u3, 0x7632);
    float l0 = v.x - __uint_as_float(u0 & 0xffff0000u);
    float l1 = v.y - __uint_as_float(u1 & 0xffff0000u);
    float l2 = v.z - __uint_as_float(u2 & 0xffff0000u);
    float l3 = v.w - __uint_as_float(u3 & 0xffff0000u);
    asm("cvt.rn.bf16x2.f32 %0, %1, %2;" : "=r"(lo01) : "f"(l1), "f"(l0));
    asm("cvt.rn.bf16x2.f32 %0, %1, %2;" : "=r"(lo23) : "f"(l3), "f"(l2));
}

static __device__ __forceinline__ void split_store(float4 v, uint32_t ahi, uint32_t alo) {
    uint32_t hi01, hi23, lo01, lo23;
    split_pack(v, hi01, hi23, lo01, lo23);
    asm volatile("st.shared.v2.b32 [%0], {%1,%2};" :: "r"(ahi), "r"(hi01), "r"(hi23) : "memory");
    asm volatile("st.shared.v2.b32 [%0], {%1,%2};" :: "r"(alo), "r"(lo01), "r"(lo23) : "memory");
}

#define LDSM4(r0, r1, r2, r3, a) \
    asm volatile("ldmatrix.sync.aligned.m8n8.x4.shared.b16 {%0,%1,%2,%3}, [%4];" \
                 : "=r"(r0), "=r"(r1), "=r"(r2), "=r"(r3) : "r"(a))

#define MMA(c, a0, a1, a2, a3, b0, b1) \
    asm volatile("mma.sync.aligned.m16n8k16.row.col.f32.bf16.bf16.f32 " \
                 "{%0,%1,%2,%3}, {%4,%5,%6,%7}, {%8,%9}, {%0,%1,%2,%3};" \
                 : "+f"((c)[0]), "+f"((c)[1]), "+f"((c)[2]), "+f"((c)[3]) \
                 : "r"(a0), "r"(a1), "r"(a2), "r"(a3), "r"(b0), "r"(b1))

// ---- prep1: blocks 0-63 split W into swizzled tiles; blocks 64-79 build g_q ----
__global__ void rbf_prep1(const float* __restrict__ in_b,
                          const float* __restrict__ centers,
                          const float* __restrict__ log_widths,
                          const float* __restrict__ out_weight,
                          const float* __restrict__ in_w)
{
    const int bid = blockIdx.x;
    const int tid = threadIdx.x;

    if (bid < 64) {
        int t = bid * 256 + tid;          // 0..16383
        int row = t >> 8;                 // h
        int c4g = t & 255;
        int ch  = c4g >> 4;
        int c4  = c4g & 15;
        float4 v = ((const float4*)in_w)[row * 256 + c4g];
        uint32_t hi01, hi23, lo01, lo23;
        split_pack(v, hi01, hi23, lo01, lo23);
        uint32_t sw = ((uint32_t)row * 128u + (uint32_t)c4 * 8u) ^ ((uint32_t)(row & 7) << 4);
        unsigned char* base = g_wt + ch * 16384;
        *(uint2*)(base + sw)        = make_uint2(hi01, hi23);
        *(uint2*)(base + 8192 + sw) = make_uint2(lo01, lo23);
        return;
    }

    const int i = (bid - 64) * 256 + tid;   // 0..4095
    const int h = i >> 6;
    float lw = log_widths[i];
    float sp = (lw > 15.f) ? lw : log1pf(expf(lw));
    float w = sp + 0.001f;
    float s = -1.4426950408889634f / (w * w);    // -log2e / w^2
    float c = centers[i] - in_b[h];              // fold bias into center
    float4 q;
    q.x = s; q.y = -2.f * s * c; q.z = s * c * c; q.w = out_weight[i];
    g_q[i] = q;
}

// ---- prep2: tabulate f_h(z) on 4096-pt grid; entry i = {f_i, f_{i+1}} ----
static __device__ __forceinline__ void tbl_store(int h, int i, const float4* qs) {
    if (i > TBLN) return;
    float z = (float)i * (1.0f / TSCALE) - 8.0f;
    float f = 0.f;
#pragma unroll 8
    for (int k = 0; k < NB; ++k) {
        float4 q = qs[k];
        float pp = fmaf(fmaf(q.x, z, q.y), z, q.z);
        float e;
        asm("ex2.approx.f32 %0, %1;" : "=f"(e) : "f"(pp));
        f = fmaf(e, q.w, f);
    }
    float* tb = (float*)(g_tbl + h * TBLN);
    if (i < TBLN) tb[2 * i] = f;            // .x of entry i
    if (i > 0)    tb[2 * i - 1] = f;        // .y of entry i-1
}

__global__ void rbf_prep2()
{
    __shared__ float4 qs[NB];
    const int h   = blockIdx.x >> 3;
    const int seg = blockIdx.x & 7;
    const int tid = threadIdx.x;
    if (tid < NB) qs[tid] = g_q[h * NB + tid];
    __syncthreads();
    int i0 = seg * 512 + tid;
    tbl_store(h, i0, qs);
    tbl_store(h, i0 + 256, qs);
    if (seg == 7 && tid == 0) tbl_store(h, TBLN, qs);
}

// ---- fused GEMM + table-lookup RBF ----
__global__ void __launch_bounds__(NT1, 2)
rbf_fused_kernel(const float* __restrict__ x,
                 const float* __restrict__ out_bias,
                 float* __restrict__ out)
{
    extern __shared__ char smem[];
    const uint32_t sb = smem_u32(smem);
    const int tid = threadIdx.x;
    const int wid = tid >> 5;
    const int l   = tid & 31;
    const int wq  = wid & 3;
    const int wh  = wid >> 2;
    const int tok0 = blockIdx.x * MTILE;

    const int r0  = tid >> 4;
    const int c4  = tid & 15;
    const uint32_t stc = (uint32_t)c4 * 8u;

    const uint32_t key  = (uint32_t)(l & 7);
    const uint32_t rowA = (uint32_t)(wq * 32 + (l & 15));
    const uint32_t chA  = (uint32_t)((l >> 4) & 1);
    const uint32_t rowB = (uint32_t)(wh * 32 + ((l >> 4) << 3) + (l & 7));
    const uint32_t chB  = (uint32_t)((l >> 3) & 1);

    float acc[2][4][4];
#pragma unroll
    for (int m = 0; m < 2; ++m)
#pragma unroll
        for (int nt = 0; nt < 4; ++nt)
#pragma unroll
            for (int j = 0; j < 4; ++j) acc[m][nt][j] = 0.f;

    const float4* xg = (const float4*)x;
    float4 pa[8];

    // ---- prologue: chunk 0 ----
    {
        const unsigned char* src = g_wt + (uint32_t)tid * 16u;
#pragma unroll
        for (int i = 0; i < 4; ++i)
            CP_ASYNC16(sb + OFF_BHI + (uint32_t)tid * 16u + i * 4096u, src + i * 4096);
        CP_COMMIT();
#pragma unroll
        for (int it = 0; it < 8; ++it)
            pa[it] = xg[(long)(tok0 + r0 + it * 16) * 256 + c4];
#pragma unroll
        for (int it = 0; it < 8; ++it) {
            int row = r0 + it * 16;
            uint32_t sw = ((uint32_t)row * 128u + stc) ^ ((uint32_t)(row & 7) << 4);
            split_store(pa[it], sb + OFF_AHI + sw, sb + OFF_ALO + sw);
        }
        CP_WAIT0();
        __syncthreads();
    }

#pragma unroll 1
    for (int ch = 0; ch < NCHUNKS; ++ch) {
        const uint32_t sbase = sb + (uint32_t)(ch & 1) * STAGE_BYTES;
        const uint32_t dbase = sb + (uint32_t)((ch + 1) & 1) * STAGE_BYTES;

        if (ch < NCHUNKS - 1) {
#pragma unroll
            for (int it = 0; it < 8; ++it)
                pa[it] = xg[(long)(tok0 + r0 + it * 16) * 256 + (ch + 1) * 16 + c4];
            const unsigned char* src = g_wt + (uint32_t)(ch + 1) * 16384u + (uint32_t)tid * 16u;
#pragma unroll
            for (int i = 0; i < 4; ++i)
                CP_ASYNC16(dbase + OFF_BHI + (uint32_t)tid * 16u + i * 4096u, src + i * 4096);
            CP_COMMIT();
        }

#pragma unroll
        for (int s = 0; s < 4; ++s) {
            const uint32_t colA = ((uint32_t)(s * 2) + chA) ^ key;
            const uint32_t colB = ((uint32_t)(s * 2) + chB) ^ key;
            uint32_t ah[2][4], al[2][4];
#pragma unroll
            for (int m = 0; m < 2; ++m) {
                uint32_t ra = (rowA + m * 16) * 128u + (colA << 4);
                LDSM4(ah[m][0], ah[m][1], ah[m][2], ah[m][3], sbase + OFF_AHI + ra);
                LDSM4(al[m][0], al[m][1], al[m][2], al[m][3], sbase + OFF_ALO + ra);
            }
#pragma unroll
            for (int np = 0; np < 2; ++np) {
                uint32_t rb = (rowB + np * 16) * 128u + (colB << 4);
                uint32_t bh[4], bl[4];
                LDSM4(bh[0], bh[1], bh[2], bh[3], sbase + OFF_BHI + rb);
                LDSM4(bl[0], bl[1], bl[2], bl[3], sbase + OFF_BHI + 8192u + rb);
#pragma unroll
                for (int m = 0; m < 2; ++m) {
                    MMA(acc[m][2 * np],     ah[m][0], ah[m][1], ah[m][2], ah[m][3], bh[0], bh[1]);
                    MMA(acc[m][2 * np + 1], ah[m][0], ah[m][1], ah[m][2], ah[m][3], bh[2], bh[3]);
                    MMA(acc[m][2 * np],     ah[m][0], ah[m][1], ah[m][2], ah[m][3], bl[0], bl[1]);
                    MMA(acc[m][2 * np + 1], ah[m][0], ah[m][1], ah[m][2], ah[m][3], bl[2], bl[3]);
                    MMA(acc[m][2 * np],     al[m][0], al[m][1], al[m][2], al[m][3], bh[0], bh[1]);
                    MMA(acc[m][2 * np + 1], al[m][0], al[m][1], al[m][2], al[m][3], bh[2], bh[3]);
                }
            }
            if (ch < NCHUNKS - 1 && s >= 2) {
#pragma unroll
                for (int j = 0; j < 4; ++j) {
                    int it = (s - 2) * 4 + j;
                    int row = r0 + it * 16;
                    uint32_t sw = ((uint32_t)row * 128u + stc) ^ ((uint32_t)(row & 7) << 4);
                    split_store(pa[it], dbase + OFF_AHI + sw, dbase + OFF_ALO + sw);
                }
            }
        }
        if (ch < NCHUNKS - 1) CP_WAIT0();
        __syncthreads();
    }

    // ---- overlay: z -> smem [128][66] ----
    {
        float* zs = (float*)(smem + OFF_ZS);
        const int g = l >> 2, t = l & 3;
#pragma unroll
        for (int m = 0; m < 2; ++m)
#pragma unroll
            for (int nt = 0; nt < 4; ++nt) {
                int tok = wq * 32 + m * 16 + g;
                int hcol = wh * 32 + nt * 8 + 2 * t;
                *(float2*)(zs + tok * 66 + hcol)       = make_float2(acc[m][nt][0], acc[m][nt][1]);
                *(float2*)(zs + (tok + 8) * 66 + hcol) = make_float2(acc[m][nt][2], acc[m][nt][3]);
            }
    }
    __syncthreads();

    // ---- epilogue: table lookup; thread = half token (32 h) ----
    const int half = tid & 1;
    const int tok  = tid >> 1;
    const float* zrow = (const float*)(smem + OFF_ZS) + tok * 66 + half * 32;
    const float2* tb = g_tbl + (half * 32) * TBLN;
    float sum = 0.f;
#pragma unroll 8
    for (int j = 0; j < 32; ++j) {
        float z = zrow[j];
        float t = fmaf(z, TSCALE, TOFF);
        int i = (int)t;
        if ((unsigned)i < (unsigned)TBLN) {
            float frac = t - (float)i;
            float2 e = __ldg(tb + j * TBLN + i);
            sum += e.x;
            sum = fmaf(frac, e.y - e.x, sum);
        } else {
            // exact fallback for |z| >= 8 (essentially never taken)
            const float4* qh = g_q + (half * 32 + j) * NB;
            float s2 = 0.f;
            for (int k = 0; k < NB; ++k) {
                float4 q = qh[k];
                float pp = fmaf(fmaf(q.x, z, q.y), z, q.z);
                float e;
                asm("ex2.approx.f32 %0, %1;" : "=f"(e) : "f"(pp));
                s2 = fmaf(e, q.w, s2);
            }
            sum += s2;
        }
    }
    sum += __shfl_xor_sync(0xffffffffu, sum, 1);
    if (half == 0) out[tok0 + tok] = sum + __ldg(out_bias);
}

extern "C" void kernel_launch(void* const* d_in, const int* in_sizes, int n_in,
                              void* d_out, int out_size)
{
    const float* x          = (const float*)d_in[0];
    const float* in_w       = (const float*)d_in[1];
    const float* in_b       = (const float*)d_in[2];
    const float* centers    = (const float*)d_in[3];
    const float* log_widths = (const float*)d_in[4];
    const float* out_weight = (const float*)d_in[5];
    const float* out_bias   = (const float*)d_in[6];
    float* out = (float*)d_out;

    int ntok = in_sizes[0] / DIMC;          // 65536

    rbf_prep1<<<80, 256>>>(in_b, centers, log_widths, out_weight, in_w);
    rbf_prep2<<<512, 256>>>();

    cudaFuncSetAttribute(rbf_fused_kernel,
                         cudaFuncAttributeMaxDynamicSharedMemorySize, SMEM_TOTAL);
    rbf_fused_kernel<<<ntok / MTILE, NT1, SMEM_TOTAL>>>(x, out_bias, out);
}

// round 15
// speedup vs baseline: 1.5477x; 1.0592x over previous
#include <cuda_runtime.h>
#include <cstdint>

#define NT1      256
#define MTILE    128
#define NCHUNKS  16
#define NH       64
#define NB       64
#define DIMC     1024

// stage layout (two stages)
#define STAGE_BYTES 49152
#define OFF_AHI  0
#define OFF_ALO  16384
#define OFF_BHI  32768          // B hi (8 KB) + B lo (8 KB) contiguous
// post-GEMM overlay
#define OFF_ZS   0              // float[128*66] = 33792 B
#define SMEM_TOTAL (2 * STAGE_BYTES)

#define TBLN     4096           // grid points over [-8, 8), step 1/256
#define TSCALE   256.0f
#define TOFF     2048.0f

__device__ float4 g_q[NH * NB];            // {s, -2sc', sc'^2, ow} (bias folded)
__device__ float2 g_tbl[NH * TBLN];        // per-h score table {f_i, f_{i+1}}
__device__ __align__(16) unsigned char g_wt[NCHUNKS * 16384];  // pre-split W tiles

static __device__ __forceinline__ uint32_t smem_u32(const void* p) {
    uint32_t a;
    asm("{ .reg .u64 t; cvta.to.shared.u64 t, %1; cvt.u32.u64 %0, t; }" : "=r"(a) : "l"(p));
    return a;
}

#define CP_ASYNC16(dst, src) \
    asm volatile("cp.async.ca.shared.global [%0], [%1], 16;" :: "r"(dst), "l"(src) : "memory")
#define CP_COMMIT() asm volatile("cp.async.commit_group;" ::: "memory")
#define CP_WAIT0()  asm volatile("cp.async.wait_group 0;" ::: "memory")

static __device__ __forceinline__ void split_pack(float4 v, uint32_t& hi01, uint32_t& hi23,
                                                  uint32_t& lo01, uint32_t& lo23) {
    uint32_t u0 = __float_as_uint(v.x), u1 = __float_as_uint(v.y);
    uint32_t u2 = __float_as_uint(v.z), u3 = __float_as_uint(v.w);
    hi01 = __byte_perm(u0, u1, 0x7632);
    hi23 = __byte_perm(u2, u3, 0x7632);
    float l0 = v.x - __uint_as_float(u0 & 0xffff0000u);
    float l1 = v.y - __uint_as_float(u1 & 0xffff0000u);
    float l2 = v.z - __uint_as_float(u2 & 0xffff0000u);
    float l3 = v.w - __uint_as_float(u3 & 0xffff0000u);
    asm("cvt.rn.bf16x2.f32 %0, %1, %2;" : "=r"(lo01) : "f"(l1), "f"(l0));
    asm("cvt.rn.bf16x2.f32 %0, %1, %2;" : "=r"(lo23) : "f"(l3), "f"(l2));
}

static __device__ __forceinline__ void split_store(float4 v, uint32_t ahi, uint32_t alo) {
    uint32_t hi01, hi23, lo01, lo23;
    split_pack(v, hi01, hi23, lo01, lo23);
    asm volatile("st.shared.v2.b32 [%0], {%1,%2};" :: "r"(ahi), "r"(hi01), "r"(hi23) : "memory");
    asm volatile("st.shared.v2.b32 [%0], {%1,%2};" :: "r"(alo), "r"(lo01), "r"(lo23) : "memory");
}

#define LDSM4(r0, r1, r2, r3, a) \
    asm volatile("ldmatrix.sync.aligned.m8n8.x4.shared.b16 {%0,%1,%2,%3}, [%4];" \
                 : "=r"(r0), "=r"(r1), "=r"(r2), "=r"(r3) : "r"(a))

#define MMA(c, a0, a1, a2, a3, b0, b1) \
    asm volatile("mma.sync.aligned.m16n8k16.row.col.f32.bf16.bf16.f32 " \
                 "{%0,%1,%2,%3}, {%4,%5,%6,%7}, {%8,%9}, {%0,%1,%2,%3};" \
                 : "+f"((c)[0]), "+f"((c)[1]), "+f"((c)[2]), "+f"((c)[3]) \
                 : "r"(a0), "r"(a1), "r"(a2), "r"(a3), "r"(b0), "r"(b1))

// ---- table point evaluator ----
static __device__ __forceinline__ void tbl_store(int h, int i, const float4* qs) {
    if (i > TBLN) return;
    float z = (float)i * (1.0f / TSCALE) - 8.0f;
    float f = 0.f;
#pragma unroll 8
    for (int k = 0; k < NB; ++k) {
        float4 q = qs[k];
        float pp = fmaf(fmaf(q.x, z, q.y), z, q.z);
        float e;
        asm("ex2.approx.f32 %0, %1;" : "=f"(e) : "f"(pp));
        f = fmaf(e, q.w, f);
    }
    float* tb = (float*)(g_tbl + h * TBLN);
    if (i < TBLN) tb[2 * i] = f;            // .x of entry i
    if (i > 0)    tb[2 * i - 1] = f;        // .y of entry i-1
}

// ---- single prep kernel: blocks 0-63 W split; blocks 64-575 coeffs + table ----
__global__ void rbf_prep(const float* __restrict__ in_b,
                         const float* __restrict__ centers,
                         const float* __restrict__ log_widths,
                         const float* __restrict__ out_weight,
                         const float* __restrict__ in_w)
{
    __shared__ float4 qs[NB];
    const int bid = blockIdx.x;
    const int tid = threadIdx.x;

    if (bid < 64) {
        int t = bid * 256 + tid;          // 0..16383
        int row = t >> 8;                 // h
        int c4g = t & 255;
        int ch  = c4g >> 4;
        int c4  = c4g & 15;
        float4 v = ((const float4*)in_w)[row * 256 + c4g];
        uint32_t hi01, hi23, lo01, lo23;
        split_pack(v, hi01, hi23, lo01, lo23);
        uint32_t sw = ((uint32_t)row * 128u + (uint32_t)c4 * 8u) ^ ((uint32_t)(row & 7) << 4);
        unsigned char* base = g_wt + ch * 16384;
        *(uint2*)(base + sw)        = make_uint2(hi01, hi23);
        *(uint2*)(base + 8192 + sw) = make_uint2(lo01, lo23);
        return;
    }

    const int t   = bid - 64;             // 0..511
    const int h   = t >> 3;
    const int seg = t & 7;

    if (tid < NB) {
        int i = h * NB + tid;
        float lw = log_widths[i];
        float sp = (lw > 15.f) ? lw : log1pf(expf(lw));
        float w = sp + 0.001f;
        float s = -1.4426950408889634f / (w * w);    // -log2e / w^2
        float c = centers[i] - in_b[h];              // fold bias into center
        float4 q;
        q.x = s; q.y = -2.f * s * c; q.z = s * c * c; q.w = out_weight[i];
        qs[tid] = q;
        if (seg == 0) g_q[i] = q;                    // publish for fallback path
    }
    __syncthreads();

    int i0 = seg * 512 + tid;
    tbl_store(h, i0, qs);
    tbl_store(h, i0 + 256, qs);
    if (seg == 7 && tid == 0) tbl_store(h, TBLN, qs);
}

// ---- fused GEMM + table-lookup RBF ----
__global__ void __launch_bounds__(NT1, 2)
rbf_fused_kernel(const float* __restrict__ x,
                 const float* __restrict__ out_bias,
                 float* __restrict__ out)
{
    extern __shared__ char smem[];
    const uint32_t sb = smem_u32(smem);
    const int tid = threadIdx.x;
    const int wid = tid >> 5;
    const int l   = tid & 31;
    const int wq  = wid & 3;
    const int wh  = wid >> 2;
    const int tok0 = blockIdx.x * MTILE;

    const int r0  = tid >> 4;
    const int c4  = tid & 15;
    const uint32_t stc = (uint32_t)c4 * 8u;

    const uint32_t key  = (uint32_t)(l & 7);
    const uint32_t rowA = (uint32_t)(wq * 32 + (l & 15));
    const uint32_t chA  = (uint32_t)((l >> 4) & 1);
    const uint32_t rowB = (uint32_t)(wh * 32 + ((l >> 4) << 3) + (l & 7));
    const uint32_t chB  = (uint32_t)((l >> 3) & 1);

    float acc[2][4][4];
#pragma unroll
    for (int m = 0; m < 2; ++m)
#pragma unroll
        for (int nt = 0; nt < 4; ++nt)
#pragma unroll
            for (int j = 0; j < 4; ++j) acc[m][nt][j] = 0.f;

    const float4* xg = (const float4*)x;
    float4 pa[8];

    // ---- prologue: chunk 0 ----
    {
        const unsigned char* src = g_wt + (uint32_t)tid * 16u;
#pragma unroll
        for (int i = 0; i < 4; ++i)
            CP_ASYNC16(sb + OFF_BHI + (uint32_t)tid * 16u + i * 4096u, src + i * 4096);
        CP_COMMIT();
#pragma unroll
        for (int it = 0; it < 8; ++it)
            pa[it] = xg[(long)(tok0 + r0 + it * 16) * 256 + c4];
#pragma unroll
        for (int it = 0; it < 8; ++it) {
            int row = r0 + it * 16;
            uint32_t sw = ((uint32_t)row * 128u + stc) ^ ((uint32_t)(row & 7) << 4);
            split_store(pa[it], sb + OFF_AHI + sw, sb + OFF_ALO + sw);
        }
        CP_WAIT0();
        __syncthreads();
    }

#pragma unroll 1
    for (int ch = 0; ch < NCHUNKS; ++ch) {
        const uint32_t sbase = sb + (uint32_t)(ch & 1) * STAGE_BYTES;
        const uint32_t dbase = sb + (uint32_t)((ch + 1) & 1) * STAGE_BYTES;

        if (ch < NCHUNKS - 1) {
#pragma unroll
            for (int it = 0; it < 8; ++it)
                pa[it] = xg[(long)(tok0 + r0 + it * 16) * 256 + (ch + 1) * 16 + c4];
            const unsigned char* src = g_wt + (uint32_t)(ch + 1) * 16384u + (uint32_t)tid * 16u;
#pragma unroll
            for (int i = 0; i < 4; ++i)
                CP_ASYNC16(dbase + OFF_BHI + (uint32_t)tid * 16u + i * 4096u, src + i * 4096);
            CP_COMMIT();
        }

#pragma unroll
        for (int s = 0; s < 4; ++s) {
            const uint32_t colA = ((uint32_t)(s * 2) + chA) ^ key;
            const uint32_t colB = ((uint32_t)(s * 2) + chB) ^ key;
            uint32_t ah[2][4], al[2][4];
#pragma unroll
            for (int m = 0; m < 2; ++m) {
                uint32_t ra = (rowA + m * 16) * 128u + (colA << 4);
                LDSM4(ah[m][0], ah[m][1], ah[m][2], ah[m][3], sbase + OFF_AHI + ra);
                LDSM4(al[m][0], al[m][1], al[m][2], al[m][3], sbase + OFF_ALO + ra);
            }
#pragma unroll
            for (int np = 0; np < 2; ++np) {
                uint32_t rb = (rowB + np * 16) * 128u + (colB << 4);
                uint32_t bh[4], bl[4];
                LDSM4(bh[0], bh[1], bh[2], bh[3], sbase + OFF_BHI + rb);
                LDSM4(bl[0], bl[1], bl[2], bl[3], sbase + OFF_BHI + 8192u + rb);
#pragma unroll
                for (int m = 0; m < 2; ++m) {
                    MMA(acc[m][2 * np],     ah[m][0], ah[m][1], ah[m][2], ah[m][3], bh[0], bh[1]);
                    MMA(acc[m][2 * np + 1], ah[m][0], ah[m][1], ah[m][2], ah[m][3], bh[2], bh[3]);
                    MMA(acc[m][2 * np],     ah[m][0], ah[m][1], ah[m][2], ah[m][3], bl[0], bl[1]);
                    MMA(acc[m][2 * np + 1], ah[m][0], ah[m][1], ah[m][2], ah[m][3], bl[2], bl[3]);
                    MMA(acc[m][2 * np],     al[m][0], al[m][1], al[m][2], al[m][3], bh[0], bh[1]);
                    MMA(acc[m][2 * np + 1], al[m][0], al[m][1], al[m][2], al[m][3], bh[2], bh[3]);
                }
            }
            // A split-stores for the next chunk, all at s==3 (max LDG slack)
            if (ch < NCHUNKS - 1 && s == 3) {
#pragma unroll
                for (int it = 0; it < 8; ++it) {
                    int row = r0 + it * 16;
                    uint32_t sw = ((uint32_t)row * 128u + stc) ^ ((uint32_t)(row & 7) << 4);
                    split_store(pa[it], dbase + OFF_AHI + sw, dbase + OFF_ALO + sw);
                }
            }
        }
        if (ch < NCHUNKS - 1) CP_WAIT0();
        __syncthreads();
    }

    // ---- overlay: z -> smem [128][66] ----
    {
        float* zs = (float*)(smem + OFF_ZS);
        const int g = l >> 2, t = l & 3;
#pragma unroll
        for (int m = 0; m < 2; ++m)
#pragma unroll
            for (int nt = 0; nt < 4; ++nt) {
                int tok = wq * 32 + m * 16 + g;
                int hcol = wh * 32 + nt * 8 + 2 * t;
                *(float2*)(zs + tok * 66 + hcol)       = make_float2(acc[m][nt][0], acc[m][nt][1]);
                *(float2*)(zs + (tok + 8) * 66 + hcol) = make_float2(acc[m][nt][2], acc[m][nt][3]);
            }
    }
    __syncthreads();

    // ---- epilogue: table lookup; thread = half token (32 h) ----
    const int half = tid & 1;
    const int tok  = tid >> 1;
    const float* zrow = (const float*)(smem + OFF_ZS) + tok * 66 + half * 32;
    const float2* tb = g_tbl + (half * 32) * TBLN;
    float sum = 0.f;
#pragma unroll 8
    for (int j = 0; j < 32; ++j) {
        float z = zrow[j];
        float t = fmaf(z, TSCALE, TOFF);
        int i = (int)t;
        if ((unsigned)i < (unsigned)TBLN) {
            float frac = t - (float)i;
            float2 e = __ldg(tb + j * TBLN + i);
            sum += e.x;
            sum = fmaf(frac, e.y - e.x, sum);
        } else {
            // exact fallback for |z| >= 8 (essentially never taken)
            const float4* qh = g_q + (half * 32 + j) * NB;
            float s2 = 0.f;
            for (int k = 0; k < NB; ++k) {
                float4 q = qh[k];
                float pp = fmaf(fmaf(q.x, z, q.y), z, q.z);
                float e;
                asm("ex2.approx.f32 %0, %1;" : "=f"(e) : "f"(pp));
                s2 = fmaf(e, q.w, s2);
            }
            sum += s2;
        }
    }
    sum += __shfl_xor_sync(0xffffffffu, sum, 1);
    if (half == 0) out[tok0 + tok] = sum + __ldg(out_bias);
}

extern "C" void kernel_launch(void* const* d_in, const int* in_sizes, int n_in,
                              void* d_out, int out_size)
{
    const float* x          = (const float*)d_in[0];
    const float* in_w       = (const float*)d_in[1];
    const float* in_b       = (const float*)d_in[2];
    const float* centers    = (const float*)d_in[3];
    const float* log_widths = (const float*)d_in[4];
    const float* out_weight = (const float*)d_in[5];
    const float* out_bias   = (const float*)d_in[6];
    float* out = (float*)d_out;

    int ntok = in_sizes[0] / DIMC;          // 65536

    rbf_prep<<<576, 256>>>(in_b, centers, log_widths, out_weight, in_w);

    cudaFuncSetAttribute(rbf_fused_kernel,
                         cudaFuncAttributeMaxDynamicSharedMemorySize, SMEM_TOTAL);
    rbf_fused_kernel<<<ntok / MTILE, NT1, SMEM_TOTAL>>>(x, out_bias, out);
}